// round 15
// baseline (speedup 1.0000x reference)
#include <cuda_runtime.h>
#include <cuda_bf16.h>
#include <cstdint>

#define SEQ    2048
#define EDIM   1024
#define G4E    4096
#define VOCABN 50257
#define NCTA   128

// ------------------------- device scratch (static, no allocs) -------------
__device__ __nv_bfloat16 g_embeds[SEQ * EDIM];            // 4 MB
__device__ __nv_bfloat16 g_Wih_b[G4E * EDIM];             // 8 MB
__device__ __nv_bfloat16 g_Whead_b[(size_t)VOCABN * EDIM];// 103 MB
__device__ float         g_xg[(size_t)SEQ * G4E];         // 32 MB
__device__ float         g_hs[SEQ * EDIM];                // 8 MB
__device__ __nv_bfloat16 g_hsb[SEQ * EDIM];               // 4 MB
__device__ float         g_bsum[G4E];
__device__ int           g_flags[NCTA];

// ------------------------- helpers ----------------------------------------
__device__ __forceinline__ float tanh_ap(float x) {
    float y; asm("tanh.approx.f32 %0, %1;" : "=f"(y) : "f"(x)); return y;
}
__device__ __forceinline__ float sigf(float x) {           // 0.5*tanh(x/2)+0.5
    return fmaf(tanh_ap(0.5f * x), 0.5f, 0.5f);
}
__device__ __forceinline__ int ld_acquire(const int* p) {
    int v; asm volatile("ld.global.acquire.gpu.b32 %0, [%1];" : "=r"(v) : "l"(p) : "memory");
    return v;
}
__device__ __forceinline__ void st_release(int* p, int v) {
    asm volatile("st.global.release.gpu.b32 [%0], %1;" :: "l"(p), "r"(v) : "memory");
}
__device__ __forceinline__ void cp_async16(uint32_t dst, const void* src) {
    asm volatile("cp.async.cg.shared.global [%0], [%1], 16;" :: "r"(dst), "l"(src) : "memory");
}
__device__ __forceinline__ void cp_async16z(uint32_t dst, const void* src, int srcbytes) {
    asm volatile("cp.async.cg.shared.global [%0], [%1], 16, %2;"
                 :: "r"(dst), "l"(src), "r"(srcbytes) : "memory");
}
__device__ __forceinline__ void mma_bf16(float* c, const uint32_t* a, const uint32_t* b) {
    asm volatile(
        "mma.sync.aligned.m16n8k16.row.col.f32.bf16.bf16.f32 "
        "{%0,%1,%2,%3}, {%4,%5,%6,%7}, {%8,%9}, {%0,%1,%2,%3};"
        : "+f"(c[0]), "+f"(c[1]), "+f"(c[2]), "+f"(c[3])
        : "r"(a[0]), "r"(a[1]), "r"(a[2]), "r"(a[3]), "r"(b[0]), "r"(b[1]));
}

// ------------------------- prep / conversion kernels -----------------------
__global__ void f2b2_kernel(const float2* __restrict__ src,
                            __nv_bfloat162* __restrict__ dst, long long n2) {
    long long i = (long long)blockIdx.x * blockDim.x + threadIdx.x;
    long long stride = (long long)gridDim.x * blockDim.x;
    for (; i < n2; i += stride) {
        float2 v = src[i];
        dst[i] = __floats2bfloat162_rn(v.x, v.y);
    }
}

__global__ void prep_kernel(const float* __restrict__ b_ih, const float* __restrict__ b_hh) {
    int i = blockIdx.x * blockDim.x + threadIdx.x;
    if (i < G4E) g_bsum[i] = b_ih[i] + b_hh[i];
    if (i < NCTA) g_flags[i] = 0;
}

// fused: blocks [0,SEQ) do embedding gather; blocks [SEQ, SEQ+2048) convert W_ih
__global__ void gather_conv_kernel(const int* __restrict__ sent,
                                   const float* __restrict__ wte,
                                   const float2* __restrict__ Wih) {
    if (blockIdx.x < SEQ) {
        int s = blockIdx.x;
        int tok = sent[s];
        const float4* src = reinterpret_cast<const float4*>(wte + (size_t)tok * EDIM);
        __nv_bfloat162* dst = reinterpret_cast<__nv_bfloat162*>(g_embeds + (size_t)s * EDIM);
        int i = threadIdx.x;             // 256 threads * 4 floats = 1024
        float4 v = src[i];
        dst[2 * i]     = __floats2bfloat162_rn(v.x, v.y);
        dst[2 * i + 1] = __floats2bfloat162_rn(v.z, v.w);
    } else {
        const long long n2 = (long long)G4E * EDIM / 2;   // 2M float2
        long long base = (long long)(blockIdx.x - SEQ) * blockDim.x + threadIdx.x;
        long long stride = 2048LL * blockDim.x;
        __nv_bfloat162* dst = reinterpret_cast<__nv_bfloat162*>(g_Wih_b);
        for (long long i = base; i < n2; i += stride) {
            float2 v = Wih[i];
            dst[i] = __floats2bfloat162_rn(v.x, v.y);
        }
    }
}

// ---------- bf16 GEMM: C[M,N] = A[M,K] * B[N,K]^T + bias[N] (fp32 out) -----
__global__ void __launch_bounds__(256) gemm_bf16(
    const __nv_bfloat16* __restrict__ A,
    const __nv_bfloat16* __restrict__ B,
    const float* __restrict__ bias,
    float* __restrict__ C,
    int M, int N, int K)
{
    constexpr int LDSH = 40;             // halves per smem row (32 + 8 pad)
    __shared__ __nv_bfloat16 As[2][128 * LDSH];
    __shared__ __nv_bfloat16 Bs[2][128 * LDSH];

    const int tid = threadIdx.x;
    const int m0 = blockIdx.y * 128;
    const int n0 = blockIdx.x * 128;

    const int lrow = tid >> 1;           // 0..127
    const int lseg = (tid & 1) * 2;      // thread loads 16B segs lseg, lseg+1

    const int wid = tid >> 5;
    const int lane = tid & 31;
    const int wm = (wid & 1) * 64;
    const int wn = (wid >> 1) * 32;
    const int g = lane >> 2;
    const int ti = lane & 3;

    float acc[4][4][4];
    #pragma unroll
    for (int a = 0; a < 4; a++)
        #pragma unroll
        for (int b = 0; b < 4; b++)
            #pragma unroll
            for (int c = 0; c < 4; c++) acc[a][b][c] = 0.f;

    const int brow = n0 + lrow;
    const int bok = (brow < N) ? 16 : 0;
    const __nv_bfloat16* Abase = A + (size_t)(m0 + lrow) * K + lseg * 8;
    const __nv_bfloat16* Bbase = B + (size_t)(brow < N ? brow : (N - 1)) * K + lseg * 8;

    const int KT = K >> 5;               // 32-wide k tiles

    {   // prologue: tile 0 -> buf 0
        uint32_t ad = (uint32_t)__cvta_generic_to_shared(&As[0][lrow * LDSH + lseg * 8]);
        uint32_t bd = (uint32_t)__cvta_generic_to_shared(&Bs[0][lrow * LDSH + lseg * 8]);
        cp_async16(ad, Abase);
        cp_async16(ad + 16, Abase + 8);
        cp_async16z(bd, Bbase, bok);
        cp_async16z(bd + 16, Bbase + 8, bok);
        asm volatile("cp.async.commit_group;" ::: "memory");
    }

    int buf = 0;
    for (int kt = 0; kt < KT; ++kt) {
        if (kt + 1 < KT) {
            int nb = buf ^ 1;
            const __nv_bfloat16* Ap = Abase + (kt + 1) * 32;
            const __nv_bfloat16* Bp = Bbase + (kt + 1) * 32;
            uint32_t ad = (uint32_t)__cvta_generic_to_shared(&As[nb][lrow * LDSH + lseg * 8]);
            uint32_t bd = (uint32_t)__cvta_generic_to_shared(&Bs[nb][lrow * LDSH + lseg * 8]);
            cp_async16(ad, Ap);
            cp_async16(ad + 16, Ap + 8);
            cp_async16z(bd, Bp, bok);
            cp_async16z(bd + 16, Bp + 8, bok);
            asm volatile("cp.async.commit_group;" ::: "memory");
            asm volatile("cp.async.wait_group 1;" ::: "memory");
        } else {
            asm volatile("cp.async.wait_group 0;" ::: "memory");
        }
        __syncthreads();

        const uint32_t* A32 = reinterpret_cast<const uint32_t*>(As[buf]);
        const uint32_t* B32 = reinterpret_cast<const uint32_t*>(Bs[buf]);
        #pragma unroll
        for (int ks = 0; ks < 2; ++ks) {
            uint32_t af[4][4], bfr[4][2];
            #pragma unroll
            for (int ms = 0; ms < 4; ++ms) {
                int r = wm + ms * 16 + g;
                af[ms][0] = A32[r * 20 + ks * 8 + ti];
                af[ms][1] = A32[(r + 8) * 20 + ks * 8 + ti];
                af[ms][2] = A32[r * 20 + ks * 8 + ti + 4];
                af[ms][3] = A32[(r + 8) * 20 + ks * 8 + ti + 4];
            }
            #pragma unroll
            for (int ns = 0; ns < 4; ++ns) {
                int r = wn + ns * 8 + g;
                bfr[ns][0] = B32[r * 20 + ks * 8 + ti];
                bfr[ns][1] = B32[r * 20 + ks * 8 + ti + 4];
            }
            #pragma unroll
            for (int ms = 0; ms < 4; ++ms)
                #pragma unroll
                for (int ns = 0; ns < 4; ++ns)
                    mma_bf16(acc[ms][ns], af[ms], bfr[ns]);
        }
        __syncthreads();
        buf ^= 1;
    }

    // epilogue: bias + fp32 store
    #pragma unroll
    for (int ms = 0; ms < 4; ++ms) {
        int row = m0 + wm + ms * 16 + g;
        #pragma unroll
        for (int ns = 0; ns < 4; ++ns) {
            int col = n0 + wn + ns * 8 + 2 * ti;
            if (col < N) {
                float bv = bias[col];
                C[(size_t)row * N + col]       = acc[ms][ns][0] + bv;
                C[(size_t)(row + 8) * N + col] = acc[ms][ns][2] + bv;
            }
            if (col + 1 < N) {
                float bv = bias[col + 1];
                C[(size_t)row * N + col + 1]       = acc[ms][ns][1] + bv;
                C[(size_t)(row + 8) * N + col + 1] = acc[ms][ns][3] + bv;
            }
        }
    }
}

// ------------------------- persistent LSTM scan ---------------------------
// 128 CTAs x 256 threads. CTA c owns h/c elements [8c,8c+8) -> 32 rows of
// W_hh register-resident (128 fp32/thread). Sync protocol = R12 (proven):
// poll all flags (tid<128), syncthreads, fence+release by tid 0.
// NEW: cooperative h staging — ONE lane-distributed LDG.128 per thread into
// smem, FMA loop reads broadcast LDS.128. Kills register batching/spills and
// 32x redundant L2 h-traffic.
__global__ void __launch_bounds__(256, 1) lstm_scan(const float* __restrict__ Whh)
{
    const int cta  = blockIdx.x;         // 0..127
    const int tid  = threadIdx.x;
    const int p    = tid >> 5;           // warp id 0..7 -> k chunk of 128
    const int lane = tid & 31;
    const int gi   = lane >> 3;          // gate 0..3 (i,f,g,o)
    const int ei   = lane & 7;           // element within CTA
    const int e0   = cta << 3;
    const int k0   = p << 7;

    // register-resident weights: W_hh[gi*E + e0+ei][k0 .. k0+128)
    float w[128];
    {
        const float4* wp = reinterpret_cast<const float4*>(
            Whh + (size_t)(gi * EDIM + e0 + ei) * EDIM + k0);
        #pragma unroll
        for (int q = 0; q < 32; ++q) {
            float4 v = wp[q];
            w[4*q] = v.x; w[4*q+1] = v.y; w[4*q+2] = v.z; w[4*q+3] = v.w;
        }
    }

    __shared__ float sh_h[8][128];       // per-warp staged h chunk
    __shared__ float part[8][32];
    float cstate = 0.f;                  // valid for tid < 8 (element owners)

    for (int t = 0; t < SEQ; ++t) {
        // x-gate contribution for owned elements (issued early, consumed late)
        float xv0 = 0.f, xv1 = 0.f, xv2 = 0.f, xv3 = 0.f;
        if (tid < 8) {
            const float* xp = g_xg + (size_t)t * G4E + e0 + tid;
            xv0 = xp[0]; xv1 = xp[EDIM]; xv2 = xp[2 * EDIM]; xv3 = xp[3 * EDIM];
        }

        float a0 = 0.f, a1 = 0.f, a2 = 0.f, a3 = 0.f;
        if (t > 0) {
            if (tid < NCTA) { while (ld_acquire(&g_flags[tid]) < t) {} }
            __syncthreads();
            // cooperative stage: lane l fetches float4 #l of this warp's chunk
            float4 hv = __ldcg(reinterpret_cast<const float4*>(
                g_hs + (size_t)(t - 1) * EDIM + k0) + lane);
            *reinterpret_cast<float4*>(&sh_h[p][lane * 4]) = hv;
            __syncwarp();
            #pragma unroll 8
            for (int q = 0; q < 32; ++q) {
                float4 v = *reinterpret_cast<const float4*>(&sh_h[p][q * 4]);
                a0 = fmaf(w[4*q],     v.x, a0);
                a1 = fmaf(w[4*q + 1], v.y, a1);
                a2 = fmaf(w[4*q + 2], v.z, a2);
                a3 = fmaf(w[4*q + 3], v.w, a3);
            }
        }
        part[p][lane] = (a0 + a1) + (a2 + a3);
        __syncthreads();

        if (tid < 32) {                  // warp 0: reduce + gates + publish
            float s = part[0][tid] + part[1][tid] + part[2][tid] + part[3][tid]
                    + part[4][tid] + part[5][tid] + part[6][tid] + part[7][tid];
            float sF = __shfl_down_sync(0xffffffffu, s, 8);
            float sG = __shfl_down_sync(0xffffffffu, s, 16);
            float sO = __shfl_down_sync(0xffffffffu, s, 24);
            if (tid < 8) {
                float gI = xv0 + s;
                float gF = xv1 + sF;
                float gG = xv2 + sG;
                float gO = xv3 + sO;
                float i_ = sigf(gI), f_ = sigf(gF), o_ = sigf(gO);
                float gg = tanh_ap(gG);
                cstate = fmaf(f_, cstate, i_ * gg);
                g_hs[(size_t)t * EDIM + e0 + tid] = o_ * tanh_ap(cstate);
            }
        }
        __syncthreads();                 // h stores visible CTA-wide; part safe
        if (tid == 0) { __threadfence(); st_release(&g_flags[cta], t + 1); }
    }
}

// ------------------------- fused log-softmax -------------------------------
// one CTA per row: max pass (DRAM), sum pass (L2-hot), subtract pass (L2-hot)
__global__ void logsoftmax_kernel(float* __restrict__ out) {
    const int row = blockIdx.x;
    const int tid = threadIdx.x;
    float* x = out + (size_t)row * VOCABN;
    __shared__ float sm[256];

    float m = -1e30f;
    for (int j = tid; j < VOCABN; j += 256) m = fmaxf(m, x[j]);
    sm[tid] = m; __syncthreads();
    for (int s = 128; s > 0; s >>= 1) {
        if (tid < s) sm[tid] = fmaxf(sm[tid], sm[tid + s]);
        __syncthreads();
    }
    float rowm = sm[0];
    __syncthreads();

    float sum = 0.f;
    for (int j = tid; j < VOCABN; j += 256) sum += __expf(x[j] - rowm);
    sm[tid] = sum; __syncthreads();
    for (int s = 128; s > 0; s >>= 1) {
        if (tid < s) sm[tid] += sm[tid + s];
        __syncthreads();
    }
    float lse = rowm + __logf(sm[0]);

    for (int j = tid; j < VOCABN; j += 256) x[j] -= lse;
}

// ------------------------- launcher ----------------------------------------
extern "C" void kernel_launch(void* const* d_in, const int* in_sizes, int n_in,
                              void* d_out, int out_size) {
    const int*   sentence = (const int*)  d_in[0];
    const float* wte      = (const float*)d_in[1];
    const float* W_ih     = (const float*)d_in[2];
    const float* W_hh     = (const float*)d_in[3];
    const float* b_ih     = (const float*)d_in[4];
    const float* b_hh     = (const float*)d_in[5];
    const float* W_head   = (const float*)d_in[6];
    const float* b_head   = (const float*)d_in[7];
    float* out = (float*)d_out;
    (void)in_sizes; (void)n_in; (void)out_size;

    __nv_bfloat16 *p_embeds, *p_Wih, *p_Whead, *p_hsb;
    float *p_xg, *p_hs, *p_bsum;
    cudaGetSymbolAddress((void**)&p_embeds, g_embeds);
    cudaGetSymbolAddress((void**)&p_Wih,    g_Wih_b);
    cudaGetSymbolAddress((void**)&p_Whead,  g_Whead_b);
    cudaGetSymbolAddress((void**)&p_hsb,    g_hsb);
    cudaGetSymbolAddress((void**)&p_xg,     g_xg);
    cudaGetSymbolAddress((void**)&p_hs,     g_hs);
    cudaGetSymbolAddress((void**)&p_bsum,   g_bsum);

    // (1) biases + flag reset
    prep_kernel<<<16, 256>>>(b_ih, b_hh);

    // (2) embedding gather + W_ih conversion (fused)
    gather_conv_kernel<<<SEQ + 2048, 256>>>(sentence, wte, (const float2*)W_ih);

    // (3) x_gates = embeds @ W_ih^T + (b_ih + b_hh)   [2048, 4096]
    {
        dim3 grid(G4E / 128, SEQ / 128);
        gemm_bf16<<<grid, 256>>>(p_embeds, p_Wih, p_bsum, p_xg, SEQ, G4E, EDIM);
    }

    // (4) sequential LSTM scan  <- target ncu capture slot
    lstm_scan<<<NCTA, 256>>>(W_hh);

    // (5) W_head -> bf16
    f2b2_kernel<<<4096, 256>>>((const float2*)W_head,
                               (__nv_bfloat162*)p_Whead,
                               (long long)VOCABN * EDIM / 2);

    // (6) hs -> bf16
    f2b2_kernel<<<1024, 256>>>((const float2*)p_hs,
                               (__nv_bfloat162*)p_hsb,
                               (long long)SEQ * EDIM / 2);

    // (7) logits = hs @ W_head^T + b_head   [2048, 50257] -> d_out
    {
        dim3 grid((VOCABN + 127) / 128, SEQ / 128);
        gemm_bf16<<<grid, 256>>>(p_hsb, p_Whead, b_head, out, SEQ, VOCABN, EDIM);
    }

    // (8) log_softmax in place (fused: max + lse + subtract)
    logsoftmax_kernel<<<SEQ, 256>>>(out);
}

// round 16
// speedup vs baseline: 2.0914x; 2.0914x over previous
#include <cuda_runtime.h>
#include <cuda_bf16.h>
#include <cstdint>

#define SEQ    2048
#define EDIM   1024
#define G4E    4096
#define VOCABN 50257
#define NCTA   128
#define FSTRIDE 32   // ints per flag slot = 128B -> one L2 line per flag

// ------------------------- device scratch (static, no allocs) -------------
__device__ __nv_bfloat16 g_embeds[SEQ * EDIM];            // 4 MB
__device__ __nv_bfloat16 g_Wih_b[G4E * EDIM];             // 8 MB
__device__ __nv_bfloat16 g_Whead_b[(size_t)VOCABN * EDIM];// 103 MB
__device__ float         g_xg[(size_t)SEQ * G4E];         // 32 MB
__device__ float         g_hs[SEQ * EDIM];                // 8 MB
__device__ __nv_bfloat16 g_hsb[SEQ * EDIM];               // 4 MB
__device__ float         g_bsum[G4E];
__device__ int           g_flags[NCTA * FSTRIDE];         // padded: 1 line/flag

// ------------------------- helpers ----------------------------------------
__device__ __forceinline__ float tanh_ap(float x) {
    float y; asm("tanh.approx.f32 %0, %1;" : "=f"(y) : "f"(x)); return y;
}
__device__ __forceinline__ float sigf(float x) {           // 0.5*tanh(x/2)+0.5
    return fmaf(tanh_ap(0.5f * x), 0.5f, 0.5f);
}
__device__ __forceinline__ int ld_acquire(const int* p) {
    int v; asm volatile("ld.global.acquire.gpu.b32 %0, [%1];" : "=r"(v) : "l"(p) : "memory");
    return v;
}
__device__ __forceinline__ void st_release(int* p, int v) {
    asm volatile("st.global.release.gpu.b32 [%0], %1;" :: "l"(p), "r"(v) : "memory");
}
__device__ __forceinline__ void cp_async16(uint32_t dst, const void* src) {
    asm volatile("cp.async.cg.shared.global [%0], [%1], 16;" :: "r"(dst), "l"(src) : "memory");
}
__device__ __forceinline__ void cp_async16z(uint32_t dst, const void* src, int srcbytes) {
    asm volatile("cp.async.cg.shared.global [%0], [%1], 16, %2;"
                 :: "r"(dst), "l"(src), "r"(srcbytes) : "memory");
}
__device__ __forceinline__ void mma_bf16(float* c, const uint32_t* a, const uint32_t* b) {
    asm volatile(
        "mma.sync.aligned.m16n8k16.row.col.f32.bf16.bf16.f32 "
        "{%0,%1,%2,%3}, {%4,%5,%6,%7}, {%8,%9}, {%0,%1,%2,%3};"
        : "+f"(c[0]), "+f"(c[1]), "+f"(c[2]), "+f"(c[3])
        : "r"(a[0]), "r"(a[1]), "r"(a[2]), "r"(a[3]), "r"(b[0]), "r"(b[1]));
}

// ------------------------- prep / conversion kernels -----------------------
__global__ void f2b2_kernel(const float2* __restrict__ src,
                            __nv_bfloat162* __restrict__ dst, long long n2) {
    long long i = (long long)blockIdx.x * blockDim.x + threadIdx.x;
    long long stride = (long long)gridDim.x * blockDim.x;
    for (; i < n2; i += stride) {
        float2 v = src[i];
        dst[i] = __floats2bfloat162_rn(v.x, v.y);
    }
}

__global__ void prep_kernel(const float* __restrict__ b_ih, const float* __restrict__ b_hh) {
    int i = blockIdx.x * blockDim.x + threadIdx.x;
    if (i < G4E) g_bsum[i] = b_ih[i] + b_hh[i];
    if (i < NCTA * FSTRIDE) g_flags[i] = 0;
}

// fused: blocks [0,SEQ) do embedding gather; blocks [SEQ, SEQ+2048) convert W_ih
__global__ void gather_conv_kernel(const int* __restrict__ sent,
                                   const float* __restrict__ wte,
                                   const float2* __restrict__ Wih) {
    if (blockIdx.x < SEQ) {
        int s = blockIdx.x;
        int tok = sent[s];
        const float4* src = reinterpret_cast<const float4*>(wte + (size_t)tok * EDIM);
        __nv_bfloat162* dst = reinterpret_cast<__nv_bfloat162*>(g_embeds + (size_t)s * EDIM);
        int i = threadIdx.x;             // 256 threads * 4 floats = 1024
        float4 v = src[i];
        dst[2 * i]     = __floats2bfloat162_rn(v.x, v.y);
        dst[2 * i + 1] = __floats2bfloat162_rn(v.z, v.w);
    } else {
        const long long n2 = (long long)G4E * EDIM / 2;   // 2M float2
        long long base = (long long)(blockIdx.x - SEQ) * blockDim.x + threadIdx.x;
        long long stride = 2048LL * blockDim.x;
        __nv_bfloat162* dst = reinterpret_cast<__nv_bfloat162*>(g_Wih_b);
        for (long long i = base; i < n2; i += stride) {
            float2 v = Wih[i];
            dst[i] = __floats2bfloat162_rn(v.x, v.y);
        }
    }
}

// ---------- bf16 GEMM: C[M,N] = A[M,K] * B[N,K]^T + bias[N] (fp32 out) -----
__global__ void __launch_bounds__(256) gemm_bf16(
    const __nv_bfloat16* __restrict__ A,
    const __nv_bfloat16* __restrict__ B,
    const float* __restrict__ bias,
    float* __restrict__ C,
    int M, int N, int K)
{
    constexpr int LDSH = 40;             // halves per smem row (32 + 8 pad)
    __shared__ __nv_bfloat16 As[2][128 * LDSH];
    __shared__ __nv_bfloat16 Bs[2][128 * LDSH];

    const int tid = threadIdx.x;
    const int m0 = blockIdx.y * 128;
    const int n0 = blockIdx.x * 128;

    const int lrow = tid >> 1;           // 0..127
    const int lseg = (tid & 1) * 2;      // thread loads 16B segs lseg, lseg+1

    const int wid = tid >> 5;
    const int lane = tid & 31;
    const int wm = (wid & 1) * 64;
    const int wn = (wid >> 1) * 32;
    const int g = lane >> 2;
    const int ti = lane & 3;

    float acc[4][4][4];
    #pragma unroll
    for (int a = 0; a < 4; a++)
        #pragma unroll
        for (int b = 0; b < 4; b++)
            #pragma unroll
            for (int c = 0; c < 4; c++) acc[a][b][c] = 0.f;

    const int brow = n0 + lrow;
    const int bok = (brow < N) ? 16 : 0;
    const __nv_bfloat16* Abase = A + (size_t)(m0 + lrow) * K + lseg * 8;
    const __nv_bfloat16* Bbase = B + (size_t)(brow < N ? brow : (N - 1)) * K + lseg * 8;

    const int KT = K >> 5;               // 32-wide k tiles

    {   // prologue: tile 0 -> buf 0
        uint32_t ad = (uint32_t)__cvta_generic_to_shared(&As[0][lrow * LDSH + lseg * 8]);
        uint32_t bd = (uint32_t)__cvta_generic_to_shared(&Bs[0][lrow * LDSH + lseg * 8]);
        cp_async16(ad, Abase);
        cp_async16(ad + 16, Abase + 8);
        cp_async16z(bd, Bbase, bok);
        cp_async16z(bd + 16, Bbase + 8, bok);
        asm volatile("cp.async.commit_group;" ::: "memory");
    }

    int buf = 0;
    for (int kt = 0; kt < KT; ++kt) {
        if (kt + 1 < KT) {
            int nb = buf ^ 1;
            const __nv_bfloat16* Ap = Abase + (kt + 1) * 32;
            const __nv_bfloat16* Bp = Bbase + (kt + 1) * 32;
            uint32_t ad = (uint32_t)__cvta_generic_to_shared(&As[nb][lrow * LDSH + lseg * 8]);
            uint32_t bd = (uint32_t)__cvta_generic_to_shared(&Bs[nb][lrow * LDSH + lseg * 8]);
            cp_async16(ad, Ap);
            cp_async16(ad + 16, Ap + 8);
            cp_async16z(bd, Bp, bok);
            cp_async16z(bd + 16, Bp + 8, bok);
            asm volatile("cp.async.commit_group;" ::: "memory");
            asm volatile("cp.async.wait_group 1;" ::: "memory");
        } else {
            asm volatile("cp.async.wait_group 0;" ::: "memory");
        }
        __syncthreads();

        const uint32_t* A32 = reinterpret_cast<const uint32_t*>(As[buf]);
        const uint32_t* B32 = reinterpret_cast<const uint32_t*>(Bs[buf]);
        #pragma unroll
        for (int ks = 0; ks < 2; ++ks) {
            uint32_t af[4][4], bfr[4][2];
            #pragma unroll
            for (int ms = 0; ms < 4; ++ms) {
                int r = wm + ms * 16 + g;
                af[ms][0] = A32[r * 20 + ks * 8 + ti];
                af[ms][1] = A32[(r + 8) * 20 + ks * 8 + ti];
                af[ms][2] = A32[r * 20 + ks * 8 + ti + 4];
                af[ms][3] = A32[(r + 8) * 20 + ks * 8 + ti + 4];
            }
            #pragma unroll
            for (int ns = 0; ns < 4; ++ns) {
                int r = wn + ns * 8 + g;
                bfr[ns][0] = B32[r * 20 + ks * 8 + ti];
                bfr[ns][1] = B32[r * 20 + ks * 8 + ti + 4];
            }
            #pragma unroll
            for (int ms = 0; ms < 4; ++ms)
                #pragma unroll
                for (int ns = 0; ns < 4; ++ns)
                    mma_bf16(acc[ms][ns], af[ms], bfr[ns]);
        }
        __syncthreads();
        buf ^= 1;
    }

    // epilogue: bias + fp32 store
    #pragma unroll
    for (int ms = 0; ms < 4; ++ms) {
        int row = m0 + wm + ms * 16 + g;
        #pragma unroll
        for (int ns = 0; ns < 4; ++ns) {
            int col = n0 + wn + ns * 8 + 2 * ti;
            if (col < N) {
                float bv = bias[col];
                C[(size_t)row * N + col]       = acc[ms][ns][0] + bv;
                C[(size_t)(row + 8) * N + col] = acc[ms][ns][2] + bv;
            }
            if (col + 1 < N) {
                float bv = bias[col + 1];
                C[(size_t)row * N + col + 1]       = acc[ms][ns][1] + bv;
                C[(size_t)(row + 8) * N + col + 1] = acc[ms][ns][3] + bv;
            }
        }
    }
}

// ------------------------- persistent LSTM scan ---------------------------
// 128 CTAs x 256 threads. CTA c owns h/c elements [8c,8c+8) -> 32 rows of
// W_hh register-resident (128 fp32/thread). R12 lock-step protocol with the
// contention fixed:
//  - flags padded to one 128B L2 line each (spread across LTS partitions)
//  - only warp 0 polls (lane l handles 4 flags, distinct lines)
//  - early warp-local release (h stores -> syncwarp -> st.release; no fence)
__global__ void __launch_bounds__(256, 1) lstm_scan(const float* __restrict__ Whh)
{
    const int cta  = blockIdx.x;         // 0..127
    const int tid  = threadIdx.x;
    const int p    = tid >> 5;           // warp id 0..7 -> k chunk of 128
    const int lane = tid & 31;
    const int gi   = lane >> 3;          // gate 0..3 (i,f,g,o)
    const int ei   = lane & 7;           // element within CTA
    const int e0   = cta << 3;
    const int k0   = p << 7;

    // register-resident weights: W_hh[gi*E + e0+ei][k0 .. k0+128)
    float w[128];
    {
        const float4* wp = reinterpret_cast<const float4*>(
            Whh + (size_t)(gi * EDIM + e0 + ei) * EDIM + k0);
        #pragma unroll
        for (int q = 0; q < 32; ++q) {
            float4 v = wp[q];
            w[4*q] = v.x; w[4*q+1] = v.y; w[4*q+2] = v.z; w[4*q+3] = v.w;
        }
    }

    __shared__ float part[8][32];
    float cstate = 0.f;                  // valid for tid < 8 (element owners)

    for (int t = 0; t < SEQ; ++t) {
        // x-gate contribution for owned elements (issued early)
        float xv0 = 0.f, xv1 = 0.f, xv2 = 0.f, xv3 = 0.f;
        if (tid < 8) {
            const float* xp = g_xg + (size_t)t * G4E + e0 + tid;
            xv0 = xp[0]; xv1 = xp[EDIM]; xv2 = xp[2 * EDIM]; xv3 = xp[3 * EDIM];
        }

        float a0 = 0.f, a1 = 0.f, a2 = 0.f, a3 = 0.f;
        if (t > 0) {
            // warp 0 polls all 128 padded flags (4 per lane, distinct lines)
            if (tid < 32) {
                #pragma unroll
                for (int j = 0; j < 4; ++j) {
                    const int* fp = &g_flags[(tid + j * 32) * FSTRIDE];
                    while (ld_acquire(fp) < t) {}
                }
            }
            __syncthreads();
            const float4* hp = reinterpret_cast<const float4*>(
                g_hs + (size_t)(t - 1) * EDIM + k0);
            #pragma unroll
            for (int q = 0; q < 32; ++q) {
                float4 v = hp[q];        // broadcast loads (R12 form)
                a0 = fmaf(w[4*q],     v.x, a0);
                a1 = fmaf(w[4*q + 1], v.y, a1);
                a2 = fmaf(w[4*q + 2], v.z, a2);
                a3 = fmaf(w[4*q + 3], v.w, a3);
            }
        }
        part[p][lane] = (a0 + a1) + (a2 + a3);
        __syncthreads();

        if (tid < 32) {                  // warp 0: reduce + gates + publish
            float s = part[0][tid] + part[1][tid] + part[2][tid] + part[3][tid]
                    + part[4][tid] + part[5][tid] + part[6][tid] + part[7][tid];
            float sF = __shfl_down_sync(0xffffffffu, s, 8);
            float sG = __shfl_down_sync(0xffffffffu, s, 16);
            float sO = __shfl_down_sync(0xffffffffu, s, 24);
            if (tid < 8) {
                float gI = xv0 + s;
                float gF = xv1 + sF;
                float gG = xv2 + sG;
                float gO = xv3 + sO;
                float i_ = sigf(gI), f_ = sigf(gF), o_ = sigf(gO);
                float gg = tanh_ap(gG);
                cstate = fmaf(f_, cstate, i_ * gg);
                g_hs[(size_t)t * EDIM + e0 + tid] = o_ * tanh_ap(cstate);
            }
            __syncwarp();                // order h stores before release
            if (tid == 0) st_release(&g_flags[cta * FSTRIDE], t + 1);
        }
        __syncthreads();                 // protect part[][] for next step
    }
}

// ------------------------- fused log-softmax -------------------------------
__global__ void logsoftmax_kernel(float* __restrict__ out) {
    const int row = blockIdx.x;
    const int tid = threadIdx.x;
    float* x = out + (size_t)row * VOCABN;
    __shared__ float sm[256];

    float m = -1e30f;
    for (int j = tid; j < VOCABN; j += 256) m = fmaxf(m, x[j]);
    sm[tid] = m; __syncthreads();
    for (int s = 128; s > 0; s >>= 1) {
        if (tid < s) sm[tid] = fmaxf(sm[tid], sm[tid + s]);
        __syncthreads();
    }
    float rowm = sm[0];
    __syncthreads();

    float sum = 0.f;
    for (int j = tid; j < VOCABN; j += 256) sum += __expf(x[j] - rowm);
    sm[tid] = sum; __syncthreads();
    for (int s = 128; s > 0; s >>= 1) {
        if (tid < s) sm[tid] += sm[tid + s];
        __syncthreads();
    }
    float lse = rowm + __logf(sm[0]);

    for (int j = tid; j < VOCABN; j += 256) x[j] -= lse;
}

// ------------------------- launcher ----------------------------------------
extern "C" void kernel_launch(void* const* d_in, const int* in_sizes, int n_in,
                              void* d_out, int out_size) {
    const int*   sentence = (const int*)  d_in[0];
    const float* wte      = (const float*)d_in[1];
    const float* W_ih     = (const float*)d_in[2];
    const float* W_hh     = (const float*)d_in[3];
    const float* b_ih     = (const float*)d_in[4];
    const float* b_hh     = (const float*)d_in[5];
    const float* W_head   = (const float*)d_in[6];
    const float* b_head   = (const float*)d_in[7];
    float* out = (float*)d_out;
    (void)in_sizes; (void)n_in; (void)out_size;

    __nv_bfloat16 *p_embeds, *p_Wih, *p_Whead, *p_hsb;
    float *p_xg, *p_hs, *p_bsum;
    cudaGetSymbolAddress((void**)&p_embeds, g_embeds);
    cudaGetSymbolAddress((void**)&p_Wih,    g_Wih_b);
    cudaGetSymbolAddress((void**)&p_Whead,  g_Whead_b);
    cudaGetSymbolAddress((void**)&p_hsb,    g_hsb);
    cudaGetSymbolAddress((void**)&p_xg,     g_xg);
    cudaGetSymbolAddress((void**)&p_hs,     g_hs);
    cudaGetSymbolAddress((void**)&p_bsum,   g_bsum);

    // (1) biases + flag reset
    prep_kernel<<<16, 256>>>(b_ih, b_hh);

    // (2) embedding gather + W_ih conversion (fused)
    gather_conv_kernel<<<SEQ + 2048, 256>>>(sentence, wte, (const float2*)W_ih);

    // (3) x_gates = embeds @ W_ih^T + (b_ih + b_hh)   [2048, 4096]
    {
        dim3 grid(G4E / 128, SEQ / 128);
        gemm_bf16<<<grid, 256>>>(p_embeds, p_Wih, p_bsum, p_xg, SEQ, G4E, EDIM);
    }

    // (4) sequential LSTM scan (persistent, padded-flag lock-step)
    lstm_scan<<<NCTA, 256>>>(W_hh);

    // (5) W_head -> bf16
    f2b2_kernel<<<4096, 256>>>((const float2*)W_head,
                               (__nv_bfloat162*)p_Whead,
                               (long long)VOCABN * EDIM / 2);

    // (6) hs -> bf16
    f2b2_kernel<<<1024, 256>>>((const float2*)p_hs,
                               (__nv_bfloat162*)p_hsb,
                               (long long)SEQ * EDIM / 2);

    // (7) logits = hs @ W_head^T + b_head   [2048, 50257] -> d_out
    {
        dim3 grid((VOCABN + 127) / 128, SEQ / 128);
        gemm_bf16<<<grid, 256>>>(p_hsb, p_Whead, b_head, out, SEQ, VOCABN, EDIM);
    }

    // (8) log_softmax in place (fused: max + lse + subtract)
    logsoftmax_kernel<<<SEQ, 256>>>(out);
}

// round 17
// speedup vs baseline: 2.1110x; 1.0093x over previous
#include <cuda_runtime.h>
#include <cuda_bf16.h>
#include <cstdint>

#define SEQ    2048
#define EDIM   1024
#define G4E    4096
#define VOCABN 50257
#define NCTA   128
#define FSTRIDE 32   // ints per flag slot = 128B -> one L2 line per flag

// ------------------------- device scratch (static, no allocs) -------------
__device__ __nv_bfloat16 g_embeds[SEQ * EDIM];            // 4 MB
__device__ __nv_bfloat16 g_Wih_b[G4E * EDIM];             // 8 MB
__device__ __nv_bfloat16 g_Whead_b[(size_t)VOCABN * EDIM];// 103 MB
__device__ float         g_xg[(size_t)SEQ * G4E];         // 32 MB
__device__ float         g_hs[SEQ * EDIM];                // 8 MB
__device__ __nv_bfloat16 g_hsb[SEQ * EDIM];               // 4 MB
__device__ float         g_bsum[G4E];
__device__ int           g_flags[NCTA * FSTRIDE];         // padded: 1 line/flag

// ------------------------- helpers ----------------------------------------
__device__ __forceinline__ float tanh_ap(float x) {
    float y; asm("tanh.approx.f32 %0, %1;" : "=f"(y) : "f"(x)); return y;
}
__device__ __forceinline__ float sigf(float x) {           // 0.5*tanh(x/2)+0.5
    return fmaf(tanh_ap(0.5f * x), 0.5f, 0.5f);
}
__device__ __forceinline__ int ld_acquire(const int* p) {
    int v; asm volatile("ld.global.acquire.gpu.b32 %0, [%1];" : "=r"(v) : "l"(p) : "memory");
    return v;
}
__device__ __forceinline__ void st_release(int* p, int v) {
    asm volatile("st.global.release.gpu.b32 [%0], %1;" :: "l"(p), "r"(v) : "memory");
}
__device__ __forceinline__ void cp_async16(uint32_t dst, const void* src) {
    asm volatile("cp.async.cg.shared.global [%0], [%1], 16;" :: "r"(dst), "l"(src) : "memory");
}
__device__ __forceinline__ void cp_async16z(uint32_t dst, const void* src, int srcbytes) {
    asm volatile("cp.async.cg.shared.global [%0], [%1], 16, %2;"
                 :: "r"(dst), "l"(src), "r"(srcbytes) : "memory");
}
__device__ __forceinline__ void mma_bf16(float* c, const uint32_t* a, const uint32_t* b) {
    asm volatile(
        "mma.sync.aligned.m16n8k16.row.col.f32.bf16.bf16.f32 "
        "{%0,%1,%2,%3}, {%4,%5,%6,%7}, {%8,%9}, {%0,%1,%2,%3};"
        : "+f"(c[0]), "+f"(c[1]), "+f"(c[2]), "+f"(c[3])
        : "r"(a[0]), "r"(a[1]), "r"(a[2]), "r"(a[3]), "r"(b[0]), "r"(b[1]));
}

// ------------------------- prep / conversion kernels -----------------------
__global__ void f2b2_kernel(const float2* __restrict__ src,
                            __nv_bfloat162* __restrict__ dst, long long n2) {
    long long i = (long long)blockIdx.x * blockDim.x + threadIdx.x;
    long long stride = (long long)gridDim.x * blockDim.x;
    for (; i < n2; i += stride) {
        float2 v = src[i];
        dst[i] = __floats2bfloat162_rn(v.x, v.y);
    }
}

__global__ void prep_kernel(const float* __restrict__ b_ih, const float* __restrict__ b_hh) {
    int i = blockIdx.x * blockDim.x + threadIdx.x;
    if (i < G4E) g_bsum[i] = b_ih[i] + b_hh[i];
    if (i < NCTA * FSTRIDE) g_flags[i] = 0;
}

// fused: blocks [0,SEQ) do embedding gather; blocks [SEQ, SEQ+2048) convert W_ih
__global__ void gather_conv_kernel(const int* __restrict__ sent,
                                   const float* __restrict__ wte,
                                   const float2* __restrict__ Wih) {
    if (blockIdx.x < SEQ) {
        int s = blockIdx.x;
        int tok = sent[s];
        const float4* src = reinterpret_cast<const float4*>(wte + (size_t)tok * EDIM);
        __nv_bfloat162* dst = reinterpret_cast<__nv_bfloat162*>(g_embeds + (size_t)s * EDIM);
        int i = threadIdx.x;             // 256 threads * 4 floats = 1024
        float4 v = src[i];
        dst[2 * i]     = __floats2bfloat162_rn(v.x, v.y);
        dst[2 * i + 1] = __floats2bfloat162_rn(v.z, v.w);
    } else {
        const long long n2 = (long long)G4E * EDIM / 2;   // 2M float2
        long long base = (long long)(blockIdx.x - SEQ) * blockDim.x + threadIdx.x;
        long long stride = 2048LL * blockDim.x;
        __nv_bfloat162* dst = reinterpret_cast<__nv_bfloat162*>(g_Wih_b);
        for (long long i = base; i < n2; i += stride) {
            float2 v = Wih[i];
            dst[i] = __floats2bfloat162_rn(v.x, v.y);
        }
    }
}

// ---------- bf16 GEMM: C[M,N] = A[M,K] * B[N,K]^T + bias[N] (fp32 out) -----
__global__ void __launch_bounds__(256) gemm_bf16(
    const __nv_bfloat16* __restrict__ A,
    const __nv_bfloat16* __restrict__ B,
    const float* __restrict__ bias,
    float* __restrict__ C,
    int M, int N, int K)
{
    constexpr int LDSH = 40;             // halves per smem row (32 + 8 pad)
    __shared__ __nv_bfloat16 As[2][128 * LDSH];
    __shared__ __nv_bfloat16 Bs[2][128 * LDSH];

    const int tid = threadIdx.x;
    const int m0 = blockIdx.y * 128;
    const int n0 = blockIdx.x * 128;

    const int lrow = tid >> 1;           // 0..127
    const int lseg = (tid & 1) * 2;      // thread loads 16B segs lseg, lseg+1

    const int wid = tid >> 5;
    const int lane = tid & 31;
    const int wm = (wid & 1) * 64;
    const int wn = (wid >> 1) * 32;
    const int g = lane >> 2;
    const int ti = lane & 3;

    float acc[4][4][4];
    #pragma unroll
    for (int a = 0; a < 4; a++)
        #pragma unroll
        for (int b = 0; b < 4; b++)
            #pragma unroll
            for (int c = 0; c < 4; c++) acc[a][b][c] = 0.f;

    const int brow = n0 + lrow;
    const int bok = (brow < N) ? 16 : 0;
    const __nv_bfloat16* Abase = A + (size_t)(m0 + lrow) * K + lseg * 8;
    const __nv_bfloat16* Bbase = B + (size_t)(brow < N ? brow : (N - 1)) * K + lseg * 8;

    const int KT = K >> 5;               // 32-wide k tiles

    {   // prologue: tile 0 -> buf 0
        uint32_t ad = (uint32_t)__cvta_generic_to_shared(&As[0][lrow * LDSH + lseg * 8]);
        uint32_t bd = (uint32_t)__cvta_generic_to_shared(&Bs[0][lrow * LDSH + lseg * 8]);
        cp_async16(ad, Abase);
        cp_async16(ad + 16, Abase + 8);
        cp_async16z(bd, Bbase, bok);
        cp_async16z(bd + 16, Bbase + 8, bok);
        asm volatile("cp.async.commit_group;" ::: "memory");
    }

    int buf = 0;
    for (int kt = 0; kt < KT; ++kt) {
        if (kt + 1 < KT) {
            int nb = buf ^ 1;
            const __nv_bfloat16* Ap = Abase + (kt + 1) * 32;
            const __nv_bfloat16* Bp = Bbase + (kt + 1) * 32;
            uint32_t ad = (uint32_t)__cvta_generic_to_shared(&As[nb][lrow * LDSH + lseg * 8]);
            uint32_t bd = (uint32_t)__cvta_generic_to_shared(&Bs[nb][lrow * LDSH + lseg * 8]);
            cp_async16(ad, Ap);
            cp_async16(ad + 16, Ap + 8);
            cp_async16z(bd, Bp, bok);
            cp_async16z(bd + 16, Bp + 8, bok);
            asm volatile("cp.async.commit_group;" ::: "memory");
            asm volatile("cp.async.wait_group 1;" ::: "memory");
        } else {
            asm volatile("cp.async.wait_group 0;" ::: "memory");
        }
        __syncthreads();

        const uint32_t* A32 = reinterpret_cast<const uint32_t*>(As[buf]);
        const uint32_t* B32 = reinterpret_cast<const uint32_t*>(Bs[buf]);
        #pragma unroll
        for (int ks = 0; ks < 2; ++ks) {
            uint32_t af[4][4], bfr[4][2];
            #pragma unroll
            for (int ms = 0; ms < 4; ++ms) {
                int r = wm + ms * 16 + g;
                af[ms][0] = A32[r * 20 + ks * 8 + ti];
                af[ms][1] = A32[(r + 8) * 20 + ks * 8 + ti];
                af[ms][2] = A32[r * 20 + ks * 8 + ti + 4];
                af[ms][3] = A32[(r + 8) * 20 + ks * 8 + ti + 4];
            }
            #pragma unroll
            for (int ns = 0; ns < 4; ++ns) {
                int r = wn + ns * 8 + g;
                bfr[ns][0] = B32[r * 20 + ks * 8 + ti];
                bfr[ns][1] = B32[r * 20 + ks * 8 + ti + 4];
            }
            #pragma unroll
            for (int ms = 0; ms < 4; ++ms)
                #pragma unroll
                for (int ns = 0; ns < 4; ++ns)
                    mma_bf16(acc[ms][ns], af[ms], bfr[ns]);
        }
        __syncthreads();
        buf ^= 1;
    }

    // epilogue: bias + fp32 store
    #pragma unroll
    for (int ms = 0; ms < 4; ++ms) {
        int row = m0 + wm + ms * 16 + g;
        #pragma unroll
        for (int ns = 0; ns < 4; ++ns) {
            int col = n0 + wn + ns * 8 + 2 * ti;
            if (col < N) {
                float bv = bias[col];
                C[(size_t)row * N + col]       = acc[ms][ns][0] + bv;
                C[(size_t)(row + 8) * N + col] = acc[ms][ns][2] + bv;
            }
            if (col + 1 < N) {
                float bv = bias[col + 1];
                C[(size_t)row * N + col + 1]       = acc[ms][ns][1] + bv;
                C[(size_t)(row + 8) * N + col + 1] = acc[ms][ns][3] + bv;
            }
        }
    }
}

// ------------------------- persistent LSTM scan ---------------------------
// 128 CTAs x 256 threads. CTA c owns h/c elements [8c,8c+8) -> 32 rows of
// W_hh register-resident (128 fp32/thread). R16 protocol, two refinements:
//  - BATCHED parallel poll: each lane loads its 4 flags per iteration (MLP=4)
//    instead of 4 serial while-loops (was ~4 serial L2 RTs on critical path)
//  - double-buffered part[][] by step parity -> tail __syncthreads dropped
__global__ void __launch_bounds__(256, 1) lstm_scan(const float* __restrict__ Whh)
{
    const int cta  = blockIdx.x;         // 0..127
    const int tid  = threadIdx.x;
    const int p    = tid >> 5;           // warp id 0..7 -> k chunk of 128
    const int lane = tid & 31;
    const int gi   = lane >> 3;          // gate 0..3 (i,f,g,o)
    const int ei   = lane & 7;           // element within CTA
    const int e0   = cta << 3;
    const int k0   = p << 7;

    // register-resident weights: W_hh[gi*E + e0+ei][k0 .. k0+128)
    float w[128];
    {
        const float4* wp = reinterpret_cast<const float4*>(
            Whh + (size_t)(gi * EDIM + e0 + ei) * EDIM + k0);
        #pragma unroll
        for (int q = 0; q < 32; ++q) {
            float4 v = wp[q];
            w[4*q] = v.x; w[4*q+1] = v.y; w[4*q+2] = v.z; w[4*q+3] = v.w;
        }
    }

    __shared__ float part[2][8][32];     // double-buffered by step parity
    float cstate = 0.f;                  // valid for tid < 8 (element owners)

    const int* fp0 = &g_flags[(lane      ) * FSTRIDE];
    const int* fp1 = &g_flags[(lane +  32) * FSTRIDE];
    const int* fp2 = &g_flags[(lane +  64) * FSTRIDE];
    const int* fp3 = &g_flags[(lane +  96) * FSTRIDE];

    for (int t = 0; t < SEQ; ++t) {
        const int pb = t & 1;
        // x-gate contribution for owned elements (issued early)
        float xv0 = 0.f, xv1 = 0.f, xv2 = 0.f, xv3 = 0.f;
        if (tid < 8) {
            const float* xp = g_xg + (size_t)t * G4E + e0 + tid;
            xv0 = xp[0]; xv1 = xp[EDIM]; xv2 = xp[2 * EDIM]; xv3 = xp[3 * EDIM];
        }

        float a0 = 0.f, a1 = 0.f, a2 = 0.f, a3 = 0.f;
        if (t > 0) {
            // warp 0: batched parallel poll of 4 flags/lane (overlapped RTs)
            if (tid < 32) {
                int v0, v1, v2, v3;
                do {
                    v0 = ld_acquire(fp0);
                    v1 = ld_acquire(fp1);
                    v2 = ld_acquire(fp2);
                    v3 = ld_acquire(fp3);
                } while ((v0 < t) | (v1 < t) | (v2 < t) | (v3 < t));
            }
            __syncthreads();             // barrier A: releases h loads
            const float4* hp = reinterpret_cast<const float4*>(
                g_hs + (size_t)(t - 1) * EDIM + k0);
            #pragma unroll
            for (int q = 0; q < 32; ++q) {
                float4 v = hp[q];        // broadcast loads
                a0 = fmaf(w[4*q],     v.x, a0);
                a1 = fmaf(w[4*q + 1], v.y, a1);
                a2 = fmaf(w[4*q + 2], v.z, a2);
                a3 = fmaf(w[4*q + 3], v.w, a3);
            }
        }
        part[pb][p][lane] = (a0 + a1) + (a2 + a3);
        __syncthreads();                 // barrier B: part[pb] complete

        if (tid < 32) {                  // warp 0: reduce + gates + publish
            float s = part[pb][0][tid] + part[pb][1][tid] + part[pb][2][tid]
                    + part[pb][3][tid] + part[pb][4][tid] + part[pb][5][tid]
                    + part[pb][6][tid] + part[pb][7][tid];
            float sF = __shfl_down_sync(0xffffffffu, s, 8);
            float sG = __shfl_down_sync(0xffffffffu, s, 16);
            float sO = __shfl_down_sync(0xffffffffu, s, 24);
            if (tid < 8) {
                float gI = xv0 + s;
                float gF = xv1 + sF;
                float gG = xv2 + sG;
                float gO = xv3 + sO;
                float i_ = sigf(gI), f_ = sigf(gF), o_ = sigf(gO);
                float gg = tanh_ap(gG);
                cstate = fmaf(f_, cstate, i_ * gg);
                g_hs[(size_t)t * EDIM + e0 + tid] = o_ * tanh_ap(cstate);
            }
            __syncwarp();                // order h stores before release
            if (tid == 0) st_release(&g_flags[cta * FSTRIDE], t + 1);
        }
        // no tail barrier: next step writes part[pb^1]; warp 0 already read pb
    }
}

// ------------------------- fused log-softmax -------------------------------
__global__ void logsoftmax_kernel(float* __restrict__ out) {
    const int row = blockIdx.x;
    const int tid = threadIdx.x;
    float* x = out + (size_t)row * VOCABN;
    __shared__ float sm[256];

    float m = -1e30f;
    for (int j = tid; j < VOCABN; j += 256) m = fmaxf(m, x[j]);
    sm[tid] = m; __syncthreads();
    for (int s = 128; s > 0; s >>= 1) {
        if (tid < s) sm[tid] = fmaxf(sm[tid], sm[tid + s]);
        __syncthreads();
    }
    float rowm = sm[0];
    __syncthreads();

    float sum = 0.f;
    for (int j = tid; j < VOCABN; j += 256) sum += __expf(x[j] - rowm);
    sm[tid] = sum; __syncthreads();
    for (int s = 128; s > 0; s >>= 1) {
        if (tid < s) sm[tid] += sm[tid + s];
        __syncthreads();
    }
    float lse = rowm + __logf(sm[0]);

    for (int j = tid; j < VOCABN; j += 256) x[j] -= lse;
}

// ------------------------- launcher ----------------------------------------
extern "C" void kernel_launch(void* const* d_in, const int* in_sizes, int n_in,
                              void* d_out, int out_size) {
    const int*   sentence = (const int*)  d_in[0];
    const float* wte      = (const float*)d_in[1];
    const float* W_ih     = (const float*)d_in[2];
    const float* W_hh     = (const float*)d_in[3];
    const float* b_ih     = (const float*)d_in[4];
    const float* b_hh     = (const float*)d_in[5];
    const float* W_head   = (const float*)d_in[6];
    const float* b_head   = (const float*)d_in[7];
    float* out = (float*)d_out;
    (void)in_sizes; (void)n_in; (void)out_size;

    __nv_bfloat16 *p_embeds, *p_Wih, *p_Whead, *p_hsb;
    float *p_xg, *p_hs, *p_bsum;
    cudaGetSymbolAddress((void**)&p_embeds, g_embeds);
    cudaGetSymbolAddress((void**)&p_Wih,    g_Wih_b);
    cudaGetSymbolAddress((void**)&p_Whead,  g_Whead_b);
    cudaGetSymbolAddress((void**)&p_hsb,    g_hsb);
    cudaGetSymbolAddress((void**)&p_xg,     g_xg);
    cudaGetSymbolAddress((void**)&p_hs,     g_hs);
    cudaGetSymbolAddress((void**)&p_bsum,   g_bsum);

    // (1) biases + flag reset
    prep_kernel<<<16, 256>>>(b_ih, b_hh);

    // (2) embedding gather + W_ih conversion (fused)
    gather_conv_kernel<<<SEQ + 2048, 256>>>(sentence, wte, (const float2*)W_ih);

    // (3) x_gates = embeds @ W_ih^T + (b_ih + b_hh)   [2048, 4096]
    {
        dim3 grid(G4E / 128, SEQ / 128);
        gemm_bf16<<<grid, 256>>>(p_embeds, p_Wih, p_bsum, p_xg, SEQ, G4E, EDIM);
    }

    // (4) sequential LSTM scan (persistent, padded-flag lock-step)
    lstm_scan<<<NCTA, 256>>>(W_hh);

    // (5) W_head -> bf16
    f2b2_kernel<<<4096, 256>>>((const float2*)W_head,
                               (__nv_bfloat162*)p_Whead,
                               (long long)VOCABN * EDIM / 2);

    // (6) hs -> bf16
    f2b2_kernel<<<1024, 256>>>((const float2*)p_hs,
                               (__nv_bfloat162*)p_hsb,
                               (long long)SEQ * EDIM / 2);

    // (7) logits = hs @ W_head^T + b_head   [2048, 50257] -> d_out
    {
        dim3 grid((VOCABN + 127) / 128, SEQ / 128);
        gemm_bf16<<<grid, 256>>>(p_hsb, p_Whead, b_head, out, SEQ, VOCABN, EDIM);
    }

    // (8) log_softmax in place (fused: max + lse + subtract)
    logsoftmax_kernel<<<SEQ, 256>>>(out);
}